// round 11
// baseline (speedup 1.0000x reference)
#include <cuda_runtime.h>
#include <cuda_fp16.h>
#include <math.h>

#define NN 20000
#define EE 320000
#define ET (EE + NN)
#define GG 64
#define FULL 0xffffffffu
#define GEMM_BLOCKS 625                   // 5000 warps / 8 per block
#define COUNT_BLOCKS ((EE / 4 + 255) / 256)

// ---------------- scratch ----------------
__device__ float  g_h[NN * 256];          // layer-1 features, fp32
__device__ __half g_x1[NN * 64];
__device__ __half g_h2[NN * 64];
__device__ float g_asrc[NN * 4];
__device__ float g_adst[NN * 4];
__device__ float g_asrc2[NN * 2];
__device__ float g_adst2[NN * 2];
__device__ int   g_cnt[NN];               // zero-init at load; re-zeroed by k_heads
__device__ int   g_off[NN + 1];
__device__ int   g_cur[NN];
__device__ int   g_csr[ET];
__device__ float g_sums[GG * 32];
__device__ float g_gcnt[GG];

__device__ __forceinline__ float lrelu(float v) { return v > 0.f ? v : 0.2f * v; }
__device__ __forceinline__ float warp_sum(float v) {
#pragma unroll
    for (int o = 16; o > 0; o >>= 1) v += __shfl_xor_sync(FULL, v, o);
    return v;
}

// packed f32x2 helpers
#define SPLAT2(out, f) asm("mov.b64 %0, {%1, %1};" : "=l"(out) : "r"(__float_as_uint(f)))
#define FMA2(acc, a, b) asm("fma.rn.f32x2 %0, %1, %2, %0;" : "+l"(acc) : "l"(a), "l"(b))
#define UNPACK2(lo, hi, in) asm("mov.b64 {%0, %1}, %2;" : "=r"(lo), "=r"(hi) : "l"(in))

// ---------------- scan (+1 self-loop; zero pooling buffers) ----------------
__global__ void k_scan(const int* __restrict__ cnt, int* __restrict__ off,
                       int* __restrict__ cur, float* __restrict__ sums,
                       float* __restrict__ gcnt) {
    __shared__ int ssum[1024];
    const int CH = 20;
    int t = threadIdx.x;
    sums[t] = 0.f; sums[t + 1024] = 0.f;
    if (t < GG) gcnt[t] = 0.f;
    int base = t * CH;
    int local[CH];
    int s = 0;
#pragma unroll
    for (int j = 0; j < CH; j++) {
        int v = (base + j < NN) ? (cnt[base + j] + 1) : 0;
        local[j] = s;
        s += v;
    }
    ssum[t] = s;
    __syncthreads();
    for (int o = 1; o < 1024; o <<= 1) {
        int v = (t >= o) ? ssum[t - o] : 0;
        __syncthreads();
        ssum[t] += v;
        __syncthreads();
    }
    int pre = ssum[t] - s;
#pragma unroll
    for (int j = 0; j < CH; j++) {
        if (base + j < NN) { off[base + j] = pre + local[j]; cur[base + j] = pre + local[j]; }
    }
    if (t == 1023) off[NN] = ssum[1023];
}

// ---------------- CSR fill ----------------
__global__ void k_build(const int* __restrict__ src, const int* __restrict__ dst,
                        int* __restrict__ cur, int* __restrict__ csr) {
    int t = blockIdx.x * blockDim.x + threadIdx.x;
    if (t < EE / 4) {
        int4 s4 = ((const int4*)src)[t];
        int4 d4 = ((const int4*)dst)[t];
        csr[atomicAdd(&cur[d4.x], 1)] = s4.x;
        csr[atomicAdd(&cur[d4.y], 1)] = s4.y;
        csr[atomicAdd(&cur[d4.z], 1)] = s4.z;
        csr[atomicAdd(&cur[d4.w], 1)] = s4.w;
    } else {
        int n = t - EE / 4;
        if (n < NN) csr[atomicAdd(&cur[n], 1)] = n;
    }
}

// ---------------- GEMM1 (fp32 in/out) + att1 + fused degree count ----------
__global__ void k_gemm1_count(const float* __restrict__ A, const float* __restrict__ B,
                              const float* __restrict__ as1, const float* __restrict__ ad1,
                              float* __restrict__ C, float* __restrict__ asrc,
                              float* __restrict__ adst,
                              const int* __restrict__ dst, int* __restrict__ cnt) {
    if (blockIdx.x >= GEMM_BLOCKS) {
        int t = (blockIdx.x - GEMM_BLOCKS) * blockDim.x + threadIdx.x;
        if (t < EE / 4) {
            int4 d4 = ((const int4*)dst)[t];
            atomicAdd(&cnt[d4.x], 1);
            atomicAdd(&cnt[d4.y], 1);
            atomicAdd(&cnt[d4.z], 1);
            atomicAdd(&cnt[d4.w], 1);
        }
        return;
    }

    int gw = blockIdx.x * 8 + (threadIdx.x >> 5);
    int lane = threadIdx.x & 31;
    int strip = gw >> 1;
    int half_ = gw & 1;
    int cg = half_ * 32 + lane;
    int row0 = strip * 8;

    const float4* A4 = (const float4*)A;
    const ulonglong2* B2 = (const ulonglong2*)B + cg;

    unsigned long long acc[8][2];
#pragma unroll
    for (int r = 0; r < 8; r++) { acc[r][0] = 0ull; acc[r][1] = 0ull; }

#pragma unroll 2
    for (int i = 0; i < 32; i++) {
        ulonglong2 b0 = B2[(4 * i + 0) * 64];
        ulonglong2 b1 = B2[(4 * i + 1) * 64];
        ulonglong2 b2 = B2[(4 * i + 2) * 64];
        ulonglong2 b3 = B2[(4 * i + 3) * 64];
#pragma unroll
        for (int r = 0; r < 8; r++) {
            float4 a = A4[(row0 + r) * 32 + i];
            unsigned long long ax, ay, az, aw;
            SPLAT2(ax, a.x); SPLAT2(ay, a.y); SPLAT2(az, a.z); SPLAT2(aw, a.w);
            FMA2(acc[r][0], ax, b0.x); FMA2(acc[r][1], ax, b0.y);
            FMA2(acc[r][0], ay, b1.x); FMA2(acc[r][1], ay, b1.y);
            FMA2(acc[r][0], az, b2.x); FMA2(acc[r][1], az, b2.y);
            FMA2(acc[r][0], aw, b3.x); FMA2(acc[r][1], aw, b3.y);
        }
    }

    float4 av = ((const float4*)as1)[cg];
    float4 dv = ((const float4*)ad1)[cg];
    float4* C4 = (float4*)C;
    float s[8], dd[8];
#pragma unroll
    for (int r = 0; r < 8; r++) {
        float4 c;
        unsigned int lo, hi;
        UNPACK2(lo, hi, acc[r][0]); c.x = __uint_as_float(lo); c.y = __uint_as_float(hi);
        UNPACK2(lo, hi, acc[r][1]); c.z = __uint_as_float(lo); c.w = __uint_as_float(hi);
        C4[(row0 + r) * 64 + cg] = c;
        s[r]  = c.x * av.x + c.y * av.y + c.z * av.z + c.w * av.w;
        dd[r] = c.x * dv.x + c.y * dv.y + c.z * dv.z + c.w * dv.w;
    }
#pragma unroll
    for (int o = 1; o < 16; o <<= 1) {
#pragma unroll
        for (int r = 0; r < 8; r++) {
            s[r]  += __shfl_xor_sync(FULL, s[r], o);
            dd[r] += __shfl_xor_sync(FULL, dd[r], o);
        }
    }
    if ((lane & 15) == 0) {
        int head = cg >> 4;
#pragma unroll
        for (int r = 0; r < 8; r++) {
            asrc[(row0 + r) * 4 + head] = s[r];
            adst[(row0 + r) * 4 + head] = dd[r];
        }
    }
}

// ---------------- layer 1 aggregation (fp32 gather, f32x2 FMA) -> x1 fp16 --
__global__ void k_agg1(const int* __restrict__ off, const int* __restrict__ csr,
                       const float* __restrict__ hfeat, const float* __restrict__ asrc,
                       const float* __restrict__ adst, const float* __restrict__ bias,
                       __half* __restrict__ x1out) {
    __shared__ int    sm_s[8][32];
    __shared__ float4 sm_w[8][32];
    int wid = threadIdx.x >> 5;
    int lane = threadIdx.x & 31;
    int d = blockIdx.x * 8 + wid;
    if (d >= NN) return;
    int b0 = off[d], b1 = off[d + 1];

    float4 adv = ((const float4*)adst)[d];
    int hh = lane >> 3;     // head of this lane (channels 8*lane..8*lane+7)

    float s0 = 0.f, s1 = 0.f, s2 = 0.f, s3 = 0.f;
    unsigned long long acc01 = 0ull, acc23 = 0ull, acc45 = 0ull, acc67 = 0ull;

    const ulonglong2* hf = (const ulonglong2*)hfeat;   // 64 per row (256 floats)
    const float4* as4 = (const float4*)asrc;
    const float* wp = (const float*)&sm_w[wid][0];

    for (int base = b0; base < b1; base += 32) {
        int k = base + lane;
        float4 w = make_float4(0.f, 0.f, 0.f, 0.f);
        int sidx = 0;
        if (k < b1) {
            sidx = csr[k];
            float4 a = as4[sidx];
            w.x = __expf(lrelu(a.x + adv.x));
            w.y = __expf(lrelu(a.y + adv.y));
            w.z = __expf(lrelu(a.z + adv.z));
            w.w = __expf(lrelu(a.w + adv.w));
            s0 += w.x; s1 += w.y; s2 += w.z; s3 += w.w;
        }
        sm_s[wid][lane] = sidx;
        sm_w[wid][lane] = w;
        __syncwarp();
        int cnt = min(32, b1 - base);
        for (int e = 0; e < cnt; e++) {
            int ss = sm_s[wid][e];
            float we = wp[e * 4 + hh];
            unsigned long long ws; SPLAT2(ws, we);
            ulonglong2 v0 = hf[ss * 64 + 2 * lane];        // channels 8L..8L+3
            ulonglong2 v1 = hf[ss * 64 + 2 * lane + 1];    // channels 8L+4..8L+7
            FMA2(acc01, ws, v0.x);
            FMA2(acc23, ws, v0.y);
            FMA2(acc45, ws, v1.x);
            FMA2(acc67, ws, v1.y);
        }
        __syncwarp();
    }

    float acc[8];
    {
        unsigned int lo, hi;
        UNPACK2(lo, hi, acc01); acc[0] = __uint_as_float(lo); acc[1] = __uint_as_float(hi);
        UNPACK2(lo, hi, acc23); acc[2] = __uint_as_float(lo); acc[3] = __uint_as_float(hi);
        UNPACK2(lo, hi, acc45); acc[4] = __uint_as_float(lo); acc[5] = __uint_as_float(hi);
        UNPACK2(lo, hi, acc67); acc[6] = __uint_as_float(lo); acc[7] = __uint_as_float(hi);
    }

    s0 = warp_sum(s0); s1 = warp_sum(s1); s2 = warp_sum(s2); s3 = warp_sum(s3);
    float iH = (hh == 0) ? 1.f / (s0 + 1e-16f)
             : (hh == 1) ? 1.f / (s1 + 1e-16f)
             : (hh == 2) ? 1.f / (s2 + 1e-16f)
             :             1.f / (s3 + 1e-16f);
#pragma unroll
    for (int j = 0; j < 8; j++) acc[j] *= iH;

#pragma unroll
    for (int j = 0; j < 8; j++) {
        acc[j] += __shfl_xor_sync(FULL, acc[j], 8);
        acc[j] += __shfl_xor_sync(FULL, acc[j], 16);
    }
    if (lane < 8) {
        float4 bb0 = ((const float4*)bias)[lane * 2];
        float4 bb1 = ((const float4*)bias)[lane * 2 + 1];
        half2 q0 = __floats2half2_rn(fmaxf(acc[0] * 0.25f + bb0.x, 0.f),
                                     fmaxf(acc[1] * 0.25f + bb0.y, 0.f));
        half2 q1 = __floats2half2_rn(fmaxf(acc[2] * 0.25f + bb0.z, 0.f),
                                     fmaxf(acc[3] * 0.25f + bb0.w, 0.f));
        half2 q2 = __floats2half2_rn(fmaxf(acc[4] * 0.25f + bb1.x, 0.f),
                                     fmaxf(acc[5] * 0.25f + bb1.y, 0.f));
        half2 q3 = __floats2half2_rn(fmaxf(acc[6] * 0.25f + bb1.z, 0.f),
                                     fmaxf(acc[7] * 0.25f + bb1.w, 0.f));
        uint4 pk;
        pk.x = *(unsigned int*)&q0;
        pk.y = *(unsigned int*)&q1;
        pk.z = *(unsigned int*)&q2;
        pk.w = *(unsigned int*)&q3;
        ((uint4*)x1out)[d * 8 + lane] = pk;
    }
}

// ---------------- GEMM2 v2: 128 nodes/block, 4-node W amortization ---------
__global__ void __launch_bounds__(256) k_gemm2(
        const __half* __restrict__ x1, const float* __restrict__ W2,
        const float* __restrict__ as2, const float* __restrict__ ad2,
        __half* __restrict__ h2out, float* __restrict__ asrc2,
        float* __restrict__ adst2) {
    __shared__ float  smW[64 * 64];          // [k][col], 16 KB
    __shared__ __half smX[128 * 68];         // [node][k] padded, 17 KB
    int t = threadIdx.x;
    int n0 = blockIdx.x * 128;

#pragma unroll
    for (int i = 0; i < 4; i++)
        ((float4*)smW)[t + 256 * i] = ((const float4*)W2)[t + 256 * i];
    {
        int row = t >> 1, part = t & 1;
        int n = n0 + row;
        const uint4* gsrc = (const uint4*)x1 + (long long)n * 8 + part * 4;
        uint2* drow = (uint2*)(smX + row * 68 + part * 32);
#pragma unroll
        for (int i = 0; i < 4; i++) {
            uint4 v = (n < NN) ? gsrc[i] : make_uint4(0, 0, 0, 0);
            drow[2 * i]     = make_uint2(v.x, v.y);
            drow[2 * i + 1] = make_uint2(v.z, v.w);
        }
    }
    __syncthreads();

    int grp = t >> 3;       // 0..31 (4 nodes each)
    int cg  = t & 7;        // col group of 8
    int nl0 = grp * 4;

    unsigned long long acc[4][4];
#pragma unroll
    for (int r = 0; r < 4; r++)
#pragma unroll
        for (int j = 0; j < 4; j++) acc[r][j] = 0ull;

    const ulonglong2* Wr = (const ulonglong2*)smW;   // 16 per k-row
#pragma unroll 4
    for (int k = 0; k < 64; k++) {
        ulonglong2 w0 = Wr[k * 16 + cg * 2];
        ulonglong2 w1 = Wr[k * 16 + cg * 2 + 1];
#pragma unroll
        for (int r = 0; r < 4; r++) {
            float xv = __half2float(smX[(nl0 + r) * 68 + k]);
            unsigned long long xs; SPLAT2(xs, xv);
            FMA2(acc[r][0], xs, w0.x); FMA2(acc[r][1], xs, w0.y);
            FMA2(acc[r][2], xs, w1.x); FMA2(acc[r][3], xs, w1.y);
        }
    }

    int hd = cg >> 2;
    const float4* a4 = (const float4*)(as2 + hd * 32 + (cg & 3) * 8);
    const float4* d4v = (const float4*)(ad2 + hd * 32 + (cg & 3) * 8);
    float4 aa0 = a4[0], aa1 = a4[1];
    float4 dd0 = d4v[0], dd1 = d4v[1];

#pragma unroll
    for (int r = 0; r < 4; r++) {
        int d = n0 + nl0 + r;
        float c[8];
        unsigned int lo, hi;
        UNPACK2(lo, hi, acc[r][0]); c[0] = __uint_as_float(lo); c[1] = __uint_as_float(hi);
        UNPACK2(lo, hi, acc[r][1]); c[2] = __uint_as_float(lo); c[3] = __uint_as_float(hi);
        UNPACK2(lo, hi, acc[r][2]); c[4] = __uint_as_float(lo); c[5] = __uint_as_float(hi);
        UNPACK2(lo, hi, acc[r][3]); c[6] = __uint_as_float(lo); c[7] = __uint_as_float(hi);
        float ps = c[0]*aa0.x + c[1]*aa0.y + c[2]*aa0.z + c[3]*aa0.w
                 + c[4]*aa1.x + c[5]*aa1.y + c[6]*aa1.z + c[7]*aa1.w;
        float pd = c[0]*dd0.x + c[1]*dd0.y + c[2]*dd0.z + c[3]*dd0.w
                 + c[4]*dd1.x + c[5]*dd1.y + c[6]*dd1.z + c[7]*dd1.w;
        ps += __shfl_xor_sync(FULL, ps, 1);
        ps += __shfl_xor_sync(FULL, ps, 2);
        pd += __shfl_xor_sync(FULL, pd, 1);
        pd += __shfl_xor_sync(FULL, pd, 2);
        if (d < NN) {
            half2 q0 = __floats2half2_rn(c[0], c[1]);
            half2 q1 = __floats2half2_rn(c[2], c[3]);
            half2 q2 = __floats2half2_rn(c[4], c[5]);
            half2 q3 = __floats2half2_rn(c[6], c[7]);
            uint4 pk;
            pk.x = *(unsigned int*)&q0;
            pk.y = *(unsigned int*)&q1;
            pk.z = *(unsigned int*)&q2;
            pk.w = *(unsigned int*)&q3;
            ((uint4*)h2out)[d * 8 + cg] = pk;
            if ((cg & 3) == 0) {
                asrc2[d * 2 + hd] = ps;
                adst2[d * 2 + hd] = pd;
            }
        }
    }
}

// ---------------- layer 2 aggregation + mean pool ---------------------------
__global__ void k_agg2(const int* __restrict__ off, const int* __restrict__ csr,
                       const __half* __restrict__ hfeat, const float* __restrict__ asrc,
                       const float* __restrict__ adst, const float* __restrict__ bias,
                       const int* __restrict__ batch, float* __restrict__ sums,
                       float* __restrict__ gcnt) {
    __shared__ int    sm_s[8][32];
    __shared__ float2 sm_w[8][32];
    int wid = threadIdx.x >> 5;
    int lane = threadIdx.x & 31;
    int d = blockIdx.x * 8 + wid;
    if (d >= NN) return;
    int b0 = off[d], b1 = off[d + 1];

    float2 adv = ((const float2*)adst)[d];
    int hh = lane >> 4;

    float s0 = 0.f, s1 = 0.f;
    float2 acc = make_float2(0.f, 0.f);
    const half2* hf = (const half2*)hfeat;
    const float2* as2p = (const float2*)asrc;
    const float* wp = (const float*)&sm_w[wid][0];

    for (int base = b0; base < b1; base += 32) {
        int k = base + lane;
        float2 w = make_float2(0.f, 0.f);
        int sidx = 0;
        if (k < b1) {
            sidx = csr[k];
            float2 a = as2p[sidx];
            w.x = __expf(lrelu(a.x + adv.x));
            w.y = __expf(lrelu(a.y + adv.y));
            s0 += w.x; s1 += w.y;
        }
        sm_s[wid][lane] = sidx;
        sm_w[wid][lane] = w;
        __syncwarp();
        int cnt = min(32, b1 - base);
        for (int e = 0; e < cnt; e++) {
            int ss = sm_s[wid][e];
            float we = wp[e * 2 + hh];
            float2 v = __half22float2(hf[ss * 32 + lane]);
            acc.x = fmaf(we, v.x, acc.x);
            acc.y = fmaf(we, v.y, acc.y);
        }
        __syncwarp();
    }

    s0 = warp_sum(s0); s1 = warp_sum(s1);
    float iH = hh ? 1.f / (s1 + 1e-16f) : 1.f / (s0 + 1e-16f);
    acc.x *= iH;
    acc.y *= iH;

    acc.x += __shfl_xor_sync(FULL, acc.x, 16);
    acc.y += __shfl_xor_sync(FULL, acc.y, 16);
    if (lane < 16) {
        const float2 b = ((const float2*)bias)[lane];
        float ox = fmaxf(acc.x * 0.5f + b.x, 0.f);
        float oy = fmaxf(acc.y * 0.5f + b.y, 0.f);
        int g = batch[d];
        atomicAdd(&sums[g * 32 + 2 * lane], ox);
        atomicAdd(&sums[g * 32 + 2 * lane + 1], oy);
        if (lane == 0) atomicAdd(&gcnt[g], 1.f);
    }
}

// ---------------- heads (+ re-zero degree counters for next replay) --------
__global__ void k_heads(const float* __restrict__ sums, const float* __restrict__ cnt,
                        const float* __restrict__ cW1, const float* __restrict__ cb1,
                        const float* __restrict__ cW2, const float* __restrict__ cb2,
                        const float* __restrict__ hW1, const float* __restrict__ hb1,
                        const float* __restrict__ hW2, const float* __restrict__ hb2,
                        float* __restrict__ out, int* __restrict__ cntz) {
    int t = threadIdx.x;
    int4 z = make_int4(0, 0, 0, 0);
    for (int i = t; i < NN / 4; i += 256) ((int4*)cntz)[i] = z;

    int g = t;
    if (g >= GG) return;
    float emb[32];
    float c_ = cnt[g];
    c_ = (c_ > 1.f) ? c_ : 1.f;
    for (int c = 0; c < 32; c++) emb[c] = sums[g * 32 + c] / c_;
    float oh = hb2[0], oc = cb2[0];
    for (int j = 0; j < 16; j++) {
        float sh = hb1[j], sc = cb1[j];
        for (int c = 0; c < 32; c++) {
            sh = fmaf(emb[c], hW1[c * 16 + j], sh);
            sc = fmaf(emb[c], cW1[c * 16 + j], sc);
        }
        sh = fmaxf(sh, 0.f);
        sc = fmaxf(sc, 0.f);
        oh = fmaf(sh, hW2[j], oh);
        oc = fmaf(sc, cW2[j], oc);
    }
    out[g]      = 1.f / (1.f + __expf(-oh));
    out[GG + g] = 1.f / (1.f + __expf(-oc));
}

// ---------------- host ----------------
static inline int cdiv(long long a, int b) { return (int)((a + b - 1) / b); }

extern "C" void kernel_launch(void* const* d_in, const int* in_sizes, int n_in,
                              void* d_out, int out_size) {
    const float* x     = (const float*)d_in[0];
    const int*   ei    = (const int*)  d_in[1];
    const int*   batch = (const int*)  d_in[2];
    const float* W1  = (const float*)d_in[3];
    const float* as1 = (const float*)d_in[4];
    const float* ad1 = (const float*)d_in[5];
    const float* b1  = (const float*)d_in[6];
    const float* W2  = (const float*)d_in[7];
    const float* as2 = (const float*)d_in[8];
    const float* ad2 = (const float*)d_in[9];
    const float* b2  = (const float*)d_in[10];
    const float* cW1 = (const float*)d_in[11];
    const float* cb1 = (const float*)d_in[12];
    const float* cW2 = (const float*)d_in[13];
    const float* cb2 = (const float*)d_in[14];
    const float* hW1 = (const float*)d_in[15];
    const float* hb1 = (const float*)d_in[16];
    const float* hW2 = (const float*)d_in[17];
    const float* hb2 = (const float*)d_in[18];

    const int* src = ei;
    const int* dst = ei + EE;

    float *p_h;
    __half *p_x1, *p_h2;
    float *p_asrc, *p_adst, *p_asrc2, *p_adst2, *p_sums, *p_gcnt;
    int *p_cnt, *p_off, *p_cur, *p_csr;
    cudaGetSymbolAddress((void**)&p_h, g_h);
    cudaGetSymbolAddress((void**)&p_x1, g_x1);
    cudaGetSymbolAddress((void**)&p_h2, g_h2);
    cudaGetSymbolAddress((void**)&p_asrc, g_asrc);
    cudaGetSymbolAddress((void**)&p_adst, g_adst);
    cudaGetSymbolAddress((void**)&p_asrc2, g_asrc2);
    cudaGetSymbolAddress((void**)&p_adst2, g_adst2);
    cudaGetSymbolAddress((void**)&p_cnt, g_cnt);
    cudaGetSymbolAddress((void**)&p_off, g_off);
    cudaGetSymbolAddress((void**)&p_cur, g_cur);
    cudaGetSymbolAddress((void**)&p_csr, g_csr);
    cudaGetSymbolAddress((void**)&p_sums, g_sums);
    cudaGetSymbolAddress((void**)&p_gcnt, g_gcnt);

    const int T = 256;

    // g_cnt is zero here (zero-init at load; k_heads re-zeroes at graph end)
    k_gemm1_count<<<GEMM_BLOCKS + COUNT_BLOCKS, T>>>(x, W1, as1, ad1, p_h,
                                                     p_asrc, p_adst, dst, p_cnt);
    k_scan<<<1, 1024>>>(p_cnt, p_off, p_cur, p_sums, p_gcnt);
    k_build<<<cdiv(EE / 4 + NN, T), T>>>(src, dst, p_cur, p_csr);

    k_agg1<<<cdiv(NN, 8), T>>>(p_off, p_csr, p_h, p_asrc, p_adst, b1, p_x1);
    k_gemm2<<<cdiv(NN, 128), T>>>(p_x1, W2, as2, ad2, p_h2, p_asrc2, p_adst2);
    k_agg2<<<cdiv(NN, 8), T>>>(p_off, p_csr, p_h2, p_asrc2, p_adst2, b2,
                               batch, p_sums, p_gcnt);
    k_heads<<<1, 256>>>(p_sums, p_gcnt, cW1, cb1, cW2, cb2, hW1, hb1, hW2, hb2,
                        (float*)d_out, p_cnt);
}

// round 12
// speedup vs baseline: 1.2543x; 1.2543x over previous
#include <cuda_runtime.h>
#include <cuda_fp16.h>
#include <math.h>

#define NN 20000
#define EE 320000
#define ET (EE + NN)
#define GG 64
#define FULL 0xffffffffu

#define MT (NN / 16)                       // 1250 m-tiles
#define APACK_BLOCKS MT                    // 1250 (320000 threads)
#define BPACK_BLOCKS 32                    // 8192 threads
#define COUNT_BLOCKS ((EE / 4 + 255) / 256) // 313

// ---------------- scratch ----------------
__device__ __half g_h[NN * 256];           // layer-1 features fp16
__device__ __half g_x1[NN * 64];
__device__ __half g_h2[NN * 64];
__device__ uint4  g_ap[MT * 8 * 32];       // A fragments (x fp16 packed), 5 MB
__device__ uint2  g_w1p[8 * 32 * 32];      // B fragments (W1 fp16 packed)
__device__ float g_asrc[NN * 4];
__device__ float g_adst[NN * 4];
__device__ float g_asrc2[NN * 2];
__device__ float g_adst2[NN * 2];
__device__ int   g_cnt[NN];                // zero at load; re-zeroed by k_heads
__device__ int   g_off[NN + 1];
__device__ int   g_cur[NN];
__device__ int   g_csr[ET];
__device__ float g_sums[GG * 32];
__device__ float g_gcnt[GG];

__device__ __forceinline__ float lrelu(float v) { return v > 0.f ? v : 0.2f * v; }
__device__ __forceinline__ float warp_sum(float v) {
#pragma unroll
    for (int o = 16; o > 0; o >>= 1) v += __shfl_xor_sync(FULL, v, o);
    return v;
}
__device__ __forceinline__ unsigned int packh2(float a, float b) {
    half2 h = __floats2half2_rn(a, b);
    return *(unsigned int*)&h;
}

__device__ __forceinline__ void mma16816(float& c0, float& c1, float& c2, float& c3,
                                         unsigned int a0, unsigned int a1,
                                         unsigned int a2, unsigned int a3,
                                         unsigned int b0, unsigned int b1) {
    asm volatile(
        "mma.sync.aligned.m16n8k16.row.col.f32.f16.f16.f32 "
        "{%0,%1,%2,%3}, {%4,%5,%6,%7}, {%8,%9}, {%0,%1,%2,%3};"
        : "+f"(c0), "+f"(c1), "+f"(c2), "+f"(c3)
        : "r"(a0), "r"(a1), "r"(a2), "r"(a3), "r"(b0), "r"(b1));
}

// ---------------- prep: pack A (x->fp16 frags), pack B (W1), degree count --
__global__ void k_prep(const float* __restrict__ x, const float* __restrict__ W1,
                       const int* __restrict__ dst, int* __restrict__ cnt) {
    int b = blockIdx.x, t = threadIdx.x;
    if (b < APACK_BLOCKS) {
        // A-pack: thread -> (mt, ks, lane)
        int gid = b * 256 + t;                 // < 320000
        int lane = gid & 31;
        int ks = (gid >> 5) & 7;
        int mt = gid >> 8;
        int gr = lane >> 2, ct = lane & 3;
        int r0 = mt * 16 + gr;
        const float2* x2 = (const float2*)x;   // [NN][64]
        float2 p00 = x2[r0 * 64 + ks * 8 + ct];
        float2 p01 = x2[r0 * 64 + ks * 8 + ct + 4];
        float2 p10 = x2[(r0 + 8) * 64 + ks * 8 + ct];
        float2 p11 = x2[(r0 + 8) * 64 + ks * 8 + ct + 4];
        uint4 frag;
        frag.x = packh2(p00.x, p00.y);         // A[gr][2ct],A[gr][2ct+1]
        frag.y = packh2(p10.x, p10.y);         // A[gr+8][2ct],A[gr+8][2ct+1]
        frag.z = packh2(p01.x, p01.y);         // A[gr][2ct+8],A[gr][2ct+9]
        frag.w = packh2(p11.x, p11.y);         // A[gr+8][2ct+8],A[gr+8][2ct+9]
        g_ap[(mt * 8 + ks) * 32 + lane] = frag;
    } else if (b < APACK_BLOCKS + BPACK_BLOCKS) {
        // B-pack: thread -> (ks, ntg, lane); W1 [128][256] row-major
        int gid = (b - APACK_BLOCKS) * 256 + t;   // < 8192
        int lane = gid & 31;
        int ntg = (gid >> 5) & 31;
        int ks = gid >> 10;
        int gr = lane >> 2, ct = lane & 3;
        int col = ntg * 8 + gr;
        int k0 = ks * 16 + 2 * ct;
        uint2 frag;
        frag.x = packh2(W1[k0 * 256 + col],       W1[(k0 + 1) * 256 + col]);
        frag.y = packh2(W1[(k0 + 8) * 256 + col], W1[(k0 + 9) * 256 + col]);
        g_w1p[(ks * 32 + ntg) * 32 + lane] = frag;
    } else {
        int gid = (b - APACK_BLOCKS - BPACK_BLOCKS) * 256 + t;
        if (gid < EE / 4) {
            int4 d4 = ((const int4*)dst)[gid];
            atomicAdd(&cnt[d4.x], 1);
            atomicAdd(&cnt[d4.y], 1);
            atomicAdd(&cnt[d4.z], 1);
            atomicAdd(&cnt[d4.w], 1);
        }
    }
}

// ---------------- tensor-core GEMM1: h = x @ W1 (fp16), + att1 -------------
// warp = 16 rows x 64 cols (one head). gw = mt*4 + w.
__global__ void __launch_bounds__(256) k_mma(const float* __restrict__ as1,
                                             const float* __restrict__ ad1,
                                             __half* __restrict__ h,
                                             float* __restrict__ asrc,
                                             float* __restrict__ adst) {
    int gw = blockIdx.x * 8 + (threadIdx.x >> 5);
    int lane = threadIdx.x & 31;
    int mt = gw >> 2;
    int w = gw & 3;                            // head / 64-col group
    if (mt >= MT) return;
    int gr = lane >> 2, ct = lane & 3;
    int row0 = mt * 16;

    uint4 a[8];
#pragma unroll
    for (int ks = 0; ks < 8; ks++) a[ks] = g_ap[(mt * 8 + ks) * 32 + lane];

    float sr = 0.f, sr8 = 0.f, dr = 0.f, dr8 = 0.f;
    half2* h2out = (half2*)h;

#pragma unroll
    for (int nt = 0; nt < 8; nt++) {
        int ntg = w * 8 + nt;
        float c0 = 0.f, c1 = 0.f, c2 = 0.f, c3 = 0.f;
#pragma unroll
        for (int ks = 0; ks < 8; ks++) {
            uint2 bfr = g_w1p[(ks * 32 + ntg) * 32 + lane];
            mma16816(c0, c1, c2, c3, a[ks].x, a[ks].y, a[ks].z, a[ks].w,
                     bfr.x, bfr.y);
        }
        // store h fp16
        h2out[(row0 + gr) * 128 + w * 32 + nt * 4 + ct]     = __floats2half2_rn(c0, c1);
        h2out[(row0 + gr + 8) * 128 + w * 32 + nt * 4 + ct] = __floats2half2_rn(c2, c3);
        // att partials
        float2 av = ((const float2*)as1)[w * 32 + nt * 4 + ct];
        float2 dv = ((const float2*)ad1)[w * 32 + nt * 4 + ct];
        sr  += c0 * av.x + c1 * av.y;
        sr8 += c2 * av.x + c3 * av.y;
        dr  += c0 * dv.x + c1 * dv.y;
        dr8 += c2 * dv.x + c3 * dv.y;
    }
    // reduce over the 4 lanes of each row group
    sr  += __shfl_xor_sync(FULL, sr, 1);  sr  += __shfl_xor_sync(FULL, sr, 2);
    sr8 += __shfl_xor_sync(FULL, sr8, 1); sr8 += __shfl_xor_sync(FULL, sr8, 2);
    dr  += __shfl_xor_sync(FULL, dr, 1);  dr  += __shfl_xor_sync(FULL, dr, 2);
    dr8 += __shfl_xor_sync(FULL, dr8, 1); dr8 += __shfl_xor_sync(FULL, dr8, 2);
    if (ct == 0) {
        asrc[(row0 + gr) * 4 + w] = sr;
        asrc[(row0 + gr + 8) * 4 + w] = sr8;
        adst[(row0 + gr) * 4 + w] = dr;
        adst[(row0 + gr + 8) * 4 + w] = dr8;
    }
}

// ---------------- scan (+1 self-loop; zero pooling buffers) ----------------
__global__ void k_scan(const int* __restrict__ cnt, int* __restrict__ off,
                       int* __restrict__ cur, float* __restrict__ sums,
                       float* __restrict__ gcnt) {
    __shared__ int ssum[1024];
    const int CH = 20;
    int t = threadIdx.x;
    sums[t] = 0.f; sums[t + 1024] = 0.f;
    if (t < GG) gcnt[t] = 0.f;
    int base = t * CH;
    int local[CH];
    int s = 0;
#pragma unroll
    for (int j = 0; j < CH; j++) {
        int v = (base + j < NN) ? (cnt[base + j] + 1) : 0;
        local[j] = s;
        s += v;
    }
    ssum[t] = s;
    __syncthreads();
    for (int o = 1; o < 1024; o <<= 1) {
        int v = (t >= o) ? ssum[t - o] : 0;
        __syncthreads();
        ssum[t] += v;
        __syncthreads();
    }
    int pre = ssum[t] - s;
#pragma unroll
    for (int j = 0; j < CH; j++) {
        if (base + j < NN) { off[base + j] = pre + local[j]; cur[base + j] = pre + local[j]; }
    }
    if (t == 1023) off[NN] = ssum[1023];
}

// ---------------- CSR fill ----------------
__global__ void k_build(const int* __restrict__ src, const int* __restrict__ dst,
                        int* __restrict__ cur, int* __restrict__ csr) {
    int t = blockIdx.x * blockDim.x + threadIdx.x;
    if (t < EE / 4) {
        int4 s4 = ((const int4*)src)[t];
        int4 d4 = ((const int4*)dst)[t];
        csr[atomicAdd(&cur[d4.x], 1)] = s4.x;
        csr[atomicAdd(&cur[d4.y], 1)] = s4.y;
        csr[atomicAdd(&cur[d4.z], 1)] = s4.z;
        csr[atomicAdd(&cur[d4.w], 1)] = s4.w;
    } else {
        int n = t - EE / 4;
        if (n < NN) csr[atomicAdd(&cur[n], 1)] = n;
    }
}

// ---------------- layer 1 aggregation (fp16 gather) -> x1 fp16 -------------
__global__ void k_agg1(const int* __restrict__ off, const int* __restrict__ csr,
                       const __half* __restrict__ hfeat, const float* __restrict__ asrc,
                       const float* __restrict__ adst, const float* __restrict__ bias,
                       __half* __restrict__ x1out) {
    __shared__ int    sm_s[8][32];
    __shared__ float4 sm_w[8][32];
    int wid = threadIdx.x >> 5;
    int lane = threadIdx.x & 31;
    int d = blockIdx.x * 8 + wid;
    if (d >= NN) return;
    int b0 = off[d], b1 = off[d + 1];

    float4 adv = ((const float4*)adst)[d];
    int hh = lane >> 3;

    float s0 = 0.f, s1 = 0.f, s2 = 0.f, s3 = 0.f;
    float acc[8];
#pragma unroll
    for (int j = 0; j < 8; j++) acc[j] = 0.f;

    const uint4* hf = (const uint4*)hfeat;
    const float4* as4 = (const float4*)asrc;
    const float* wp = (const float*)&sm_w[wid][0];

    for (int base = b0; base < b1; base += 32) {
        int k = base + lane;
        float4 w = make_float4(0.f, 0.f, 0.f, 0.f);
        int sidx = 0;
        if (k < b1) {
            sidx = csr[k];
            float4 a = as4[sidx];
            w.x = __expf(lrelu(a.x + adv.x));
            w.y = __expf(lrelu(a.y + adv.y));
            w.z = __expf(lrelu(a.z + adv.z));
            w.w = __expf(lrelu(a.w + adv.w));
            s0 += w.x; s1 += w.y; s2 += w.z; s3 += w.w;
        }
        sm_s[wid][lane] = sidx;
        sm_w[wid][lane] = w;
        __syncwarp();
        int cnt = min(32, b1 - base);
        for (int e = 0; e < cnt; e++) {
            int ss = sm_s[wid][e];
            float we = wp[e * 4 + hh];
            uint4 v = hf[ss * 32 + lane];
            float2 p;
            p = __half22float2(*(half2*)&v.x); acc[0] = fmaf(we, p.x, acc[0]); acc[1] = fmaf(we, p.y, acc[1]);
            p = __half22float2(*(half2*)&v.y); acc[2] = fmaf(we, p.x, acc[2]); acc[3] = fmaf(we, p.y, acc[3]);
            p = __half22float2(*(half2*)&v.z); acc[4] = fmaf(we, p.x, acc[4]); acc[5] = fmaf(we, p.y, acc[5]);
            p = __half22float2(*(half2*)&v.w); acc[6] = fmaf(we, p.x, acc[6]); acc[7] = fmaf(we, p.y, acc[7]);
        }
        __syncwarp();
    }

    s0 = warp_sum(s0); s1 = warp_sum(s1); s2 = warp_sum(s2); s3 = warp_sum(s3);
    float iH = (hh == 0) ? 1.f / (s0 + 1e-16f)
             : (hh == 1) ? 1.f / (s1 + 1e-16f)
             : (hh == 2) ? 1.f / (s2 + 1e-16f)
             :             1.f / (s3 + 1e-16f);
#pragma unroll
    for (int j = 0; j < 8; j++) acc[j] *= iH;

#pragma unroll
    for (int j = 0; j < 8; j++) {
        acc[j] += __shfl_xor_sync(FULL, acc[j], 8);
        acc[j] += __shfl_xor_sync(FULL, acc[j], 16);
    }
    if (lane < 8) {
        float4 bb0 = ((const float4*)bias)[lane * 2];
        float4 bb1 = ((const float4*)bias)[lane * 2 + 1];
        uint4 pk;
        pk.x = packh2(fmaxf(acc[0] * 0.25f + bb0.x, 0.f), fmaxf(acc[1] * 0.25f + bb0.y, 0.f));
        pk.y = packh2(fmaxf(acc[2] * 0.25f + bb0.z, 0.f), fmaxf(acc[3] * 0.25f + bb0.w, 0.f));
        pk.z = packh2(fmaxf(acc[4] * 0.25f + bb1.x, 0.f), fmaxf(acc[5] * 0.25f + bb1.y, 0.f));
        pk.w = packh2(fmaxf(acc[6] * 0.25f + bb1.z, 0.f), fmaxf(acc[7] * 0.25f + bb1.w, 0.f));
        ((uint4*)x1out)[d * 8 + lane] = pk;
    }
}

// ---------------- GEMM2 v2: 128 nodes/block, 4-node W amortization ---------
#define SPLAT2(out, f) asm("mov.b64 %0, {%1, %1};" : "=l"(out) : "r"(__float_as_uint(f)))
#define FMA2(acc, a, b) asm("fma.rn.f32x2 %0, %1, %2, %0;" : "+l"(acc) : "l"(a), "l"(b))
#define UNPACK2(lo, hi, in) asm("mov.b64 {%0, %1}, %2;" : "=r"(lo), "=r"(hi) : "l"(in))

__global__ void __launch_bounds__(256) k_gemm2(
        const __half* __restrict__ x1, const float* __restrict__ W2,
        const float* __restrict__ as2, const float* __restrict__ ad2,
        __half* __restrict__ h2out, float* __restrict__ asrc2,
        float* __restrict__ adst2) {
    __shared__ float  smW[64 * 64];
    __shared__ __half smX[128 * 68];
    int t = threadIdx.x;
    int n0 = blockIdx.x * 128;

#pragma unroll
    for (int i = 0; i < 4; i++)
        ((float4*)smW)[t + 256 * i] = ((const float4*)W2)[t + 256 * i];
    {
        int row = t >> 1, part = t & 1;
        int n = n0 + row;
        const uint4* gsrc = (const uint4*)x1 + (long long)n * 8 + part * 4;
        uint2* drow = (uint2*)(smX + row * 68 + part * 32);
#pragma unroll
        for (int i = 0; i < 4; i++) {
            uint4 v = (n < NN) ? gsrc[i] : make_uint4(0, 0, 0, 0);
            drow[2 * i]     = make_uint2(v.x, v.y);
            drow[2 * i + 1] = make_uint2(v.z, v.w);
        }
    }
    __syncthreads();

    int grp = t >> 3;
    int cg  = t & 7;
    int nl0 = grp * 4;

    unsigned long long acc[4][4];
#pragma unroll
    for (int r = 0; r < 4; r++)
#pragma unroll
        for (int j = 0; j < 4; j++) acc[r][j] = 0ull;

    const ulonglong2* Wr = (const ulonglong2*)smW;
#pragma unroll 4
    for (int k = 0; k < 64; k++) {
        ulonglong2 w0 = Wr[k * 16 + cg * 2];
        ulonglong2 w1 = Wr[k * 16 + cg * 2 + 1];
#pragma unroll
        for (int r = 0; r < 4; r++) {
            float xv = __half2float(smX[(nl0 + r) * 68 + k]);
            unsigned long long xs; SPLAT2(xs, xv);
            FMA2(acc[r][0], xs, w0.x); FMA2(acc[r][1], xs, w0.y);
            FMA2(acc[r][2], xs, w1.x); FMA2(acc[r][3], xs, w1.y);
        }
    }

    int hd = cg >> 2;
    const float4* a4 = (const float4*)(as2 + hd * 32 + (cg & 3) * 8);
    const float4* d4v = (const float4*)(ad2 + hd * 32 + (cg & 3) * 8);
    float4 aa0 = a4[0], aa1 = a4[1];
    float4 dd0 = d4v[0], dd1 = d4v[1];

#pragma unroll
    for (int r = 0; r < 4; r++) {
        int d = n0 + nl0 + r;
        float c[8];
        unsigned int lo, hi;
        UNPACK2(lo, hi, acc[r][0]); c[0] = __uint_as_float(lo); c[1] = __uint_as_float(hi);
        UNPACK2(lo, hi, acc[r][1]); c[2] = __uint_as_float(lo); c[3] = __uint_as_float(hi);
        UNPACK2(lo, hi, acc[r][2]); c[4] = __uint_as_float(lo); c[5] = __uint_as_float(hi);
        UNPACK2(lo, hi, acc[r][3]); c[6] = __uint_as_float(lo); c[7] = __uint_as_float(hi);
        float ps = c[0]*aa0.x + c[1]*aa0.y + c[2]*aa0.z + c[3]*aa0.w
                 + c[4]*aa1.x + c[5]*aa1.y + c[6]*aa1.z + c[7]*aa1.w;
        float pd = c[0]*dd0.x + c[1]*dd0.y + c[2]*dd0.z + c[3]*dd0.w
                 + c[4]*dd1.x + c[5]*dd1.y + c[6]*dd1.z + c[7]*dd1.w;
        ps += __shfl_xor_sync(FULL, ps, 1);
        ps += __shfl_xor_sync(FULL, ps, 2);
        pd += __shfl_xor_sync(FULL, pd, 1);
        pd += __shfl_xor_sync(FULL, pd, 2);
        if (d < NN) {
            uint4 pk;
            pk.x = packh2(c[0], c[1]);
            pk.y = packh2(c[2], c[3]);
            pk.z = packh2(c[4], c[5]);
            pk.w = packh2(c[6], c[7]);
            ((uint4*)h2out)[d * 8 + cg] = pk;
            if ((cg & 3) == 0) {
                asrc2[d * 2 + hd] = ps;
                adst2[d * 2 + hd] = pd;
            }
        }
    }
}

// ---------------- layer 2 aggregation + mean pool ---------------------------
__global__ void k_agg2(const int* __restrict__ off, const int* __restrict__ csr,
                       const __half* __restrict__ hfeat, const float* __restrict__ asrc,
                       const float* __restrict__ adst, const float* __restrict__ bias,
                       const int* __restrict__ batch, float* __restrict__ sums,
                       float* __restrict__ gcnt) {
    __shared__ int    sm_s[8][32];
    __shared__ float2 sm_w[8][32];
    int wid = threadIdx.x >> 5;
    int lane = threadIdx.x & 31;
    int d = blockIdx.x * 8 + wid;
    if (d >= NN) return;
    int b0 = off[d], b1 = off[d + 1];

    float2 adv = ((const float2*)adst)[d];
    int hh = lane >> 4;

    float s0 = 0.f, s1 = 0.f;
    float2 acc = make_float2(0.f, 0.f);
    const half2* hf = (const half2*)hfeat;
    const float2* as2p = (const float2*)asrc;
    const float* wp = (const float*)&sm_w[wid][0];

    for (int base = b0; base < b1; base += 32) {
        int k = base + lane;
        float2 w = make_float2(0.f, 0.f);
        int sidx = 0;
        if (k < b1) {
            sidx = csr[k];
            float2 a = as2p[sidx];
            w.x = __expf(lrelu(a.x + adv.x));
            w.y = __expf(lrelu(a.y + adv.y));
            s0 += w.x; s1 += w.y;
        }
        sm_s[wid][lane] = sidx;
        sm_w[wid][lane] = w;
        __syncwarp();
        int cnt = min(32, b1 - base);
        for (int e = 0; e < cnt; e++) {
            int ss = sm_s[wid][e];
            float we = wp[e * 2 + hh];
            float2 v = __half22float2(hf[ss * 32 + lane]);
            acc.x = fmaf(we, v.x, acc.x);
            acc.y = fmaf(we, v.y, acc.y);
        }
        __syncwarp();
    }

    s0 = warp_sum(s0); s1 = warp_sum(s1);
    float iH = hh ? 1.f / (s1 + 1e-16f) : 1.f / (s0 + 1e-16f);
    acc.x *= iH;
    acc.y *= iH;

    acc.x += __shfl_xor_sync(FULL, acc.x, 16);
    acc.y += __shfl_xor_sync(FULL, acc.y, 16);
    if (lane < 16) {
        const float2 b = ((const float2*)bias)[lane];
        float ox = fmaxf(acc.x * 0.5f + b.x, 0.f);
        float oy = fmaxf(acc.y * 0.5f + b.y, 0.f);
        int g = batch[d];
        atomicAdd(&sums[g * 32 + 2 * lane], ox);
        atomicAdd(&sums[g * 32 + 2 * lane + 1], oy);
        if (lane == 0) atomicAdd(&gcnt[g], 1.f);
    }
}

// ---------------- heads (+ re-zero degree counters) ----------------
__global__ void k_heads(const float* __restrict__ sums, const float* __restrict__ cnt,
                        const float* __restrict__ cW1, const float* __restrict__ cb1,
                        const float* __restrict__ cW2, const float* __restrict__ cb2,
                        const float* __restrict__ hW1, const float* __restrict__ hb1,
                        const float* __restrict__ hW2, const float* __restrict__ hb2,
                        float* __restrict__ out, int* __restrict__ cntz) {
    int t = threadIdx.x;
    int4 z = make_int4(0, 0, 0, 0);
    for (int i = t; i < NN / 4; i += 256) ((int4*)cntz)[i] = z;

    int g = t;
    if (g >= GG) return;
    float emb[32];
    float c_ = cnt[g];
    c_ = (c_ > 1.f) ? c_ : 1.f;
    for (int c = 0; c < 32; c++) emb[c] = sums[g * 32 + c] / c_;
    float oh = hb2[0], oc = cb2[0];
    for (int j = 0; j < 16; j++) {
        float sh = hb1[j], sc = cb1[j];
        for (int c = 0; c < 32; c++) {
            sh = fmaf(emb[c], hW1[c * 16 + j], sh);
            sc = fmaf(emb[c], cW1[c * 16 + j], sc);
        }
        sh = fmaxf(sh, 0.f);
        sc = fmaxf(sc, 0.f);
        oh = fmaf(sh, hW2[j], oh);
        oc = fmaf(sc, cW2[j], oc);
    }
    out[g]      = 1.f / (1.f + __expf(-oh));
    out[GG + g] = 1.f / (1.f + __expf(-oc));
}

// ---------------- host ----------------
static inline int cdiv(long long a, int b) { return (int)((a + b - 1) / b); }

extern "C" void kernel_launch(void* const* d_in, const int* in_sizes, int n_in,
                              void* d_out, int out_size) {
    const float* x     = (const float*)d_in[0];
    const int*   ei    = (const int*)  d_in[1];
    const int*   batch = (const int*)  d_in[2];
    const float* W1  = (const float*)d_in[3];
    const float* as1 = (const float*)d_in[4];
    const float* ad1 = (const float*)d_in[5];
    const float* b1  = (const float*)d_in[6];
    const float* W2  = (const float*)d_in[7];
    const float* as2 = (const float*)d_in[8];
    const float* ad2 = (const float*)d_in[9];
    const float* b2  = (const float*)d_in[10];
    const float* cW1 = (const float*)d_in[11];
    const float* cb1 = (const float*)d_in[12];
    const float* cW2 = (const float*)d_in[13];
    const float* cb2 = (const float*)d_in[14];
    const float* hW1 = (const float*)d_in[15];
    const float* hb1 = (const float*)d_in[16];
    const float* hW2 = (const float*)d_in[17];
    const float* hb2 = (const float*)d_in[18];

    const int* src = ei;
    const int* dst = ei + EE;

    __half *p_h, *p_x1, *p_h2;
    float *p_asrc, *p_adst, *p_asrc2, *p_adst2, *p_sums, *p_gcnt;
    int *p_cnt, *p_off, *p_cur, *p_csr;
    cudaGetSymbolAddress((void**)&p_h, g_h);
    cudaGetSymbolAddress((void**)&p_x1, g_x1);
    cudaGetSymbolAddress((void**)&p_h2, g_h2);
    cudaGetSymbolAddress((void**)&p_asrc, g_asrc);
    cudaGetSymbolAddress((void**)&p_adst, g_adst);
    cudaGetSymbolAddress((void**)&p_asrc2, g_asrc2);
    cudaGetSymbolAddress((void**)&p_adst2, g_adst2);
    cudaGetSymbolAddress((void**)&p_cnt, g_cnt);
    cudaGetSymbolAddress((void**)&p_off, g_off);
    cudaGetSymbolAddress((void**)&p_cur, g_cur);
    cudaGetSymbolAddress((void**)&p_csr, g_csr);
    cudaGetSymbolAddress((void**)&p_sums, g_sums);
    cudaGetSymbolAddress((void**)&p_gcnt, g_gcnt);

    const int T = 256;

    // pack A/B fragments + degree count (g_cnt zero at entry)
    k_prep<<<APACK_BLOCKS + BPACK_BLOCKS + COUNT_BLOCKS, T>>>(x, W1, dst, p_cnt);
    // tensor-core GEMM1 + att1
    k_mma<<<cdiv(MT * 4, 8), T>>>(as1, ad1, p_h, p_asrc, p_adst);
    k_scan<<<1, 1024>>>(p_cnt, p_off, p_cur, p_sums, p_gcnt);
    k_build<<<cdiv(EE / 4 + NN, T), T>>>(src, dst, p_cur, p_csr);

    k_agg1<<<cdiv(NN, 8), T>>>(p_off, p_csr, p_h, p_asrc, p_adst, b1, p_x1);
    k_gemm2<<<cdiv(NN, 128), T>>>(p_x1, W2, as2, ad2, p_h2, p_asrc2, p_adst2);
    k_agg2<<<cdiv(NN, 8), T>>>(p_off, p_csr, p_h2, p_asrc2, p_adst2, b2,
                               batch, p_sums, p_gcnt);
    k_heads<<<1, 256>>>(p_sums, p_gcnt, cW1, cb1, cW2, cb2, hW1, hb1, hW2, hb2,
                        (float*)d_out, p_cnt);
}

// round 13
// speedup vs baseline: 1.2546x; 1.0002x over previous
#include <cuda_runtime.h>
#include <cuda_fp16.h>
#include <math.h>

#define NN 20000
#define EE 320000
#define ET (EE + NN)
#define GG 64
#define FULL 0xffffffffu

#define MT (NN / 16)                        // 1250 m-tiles
#define APACK_BLOCKS MT                     // 1250
#define BPACK_BLOCKS 32
#define COUNT_BLOCKS ((EE / 4 + 255) / 256) // 313
#define MMA_BLOCKS ((MT * 4 + 7) / 8)       // 625
#define BUILD_BLOCKS ((EE / 4 + NN + 255) / 256)  // 391
#define AGG2_BLOCKS ((NN + 7) / 8)          // 2500

// ---------------- scratch ----------------
__device__ __half g_h[NN * 256];
__device__ __half g_x1[NN * 64];
__device__ __half g_h2[NN * 64];
__device__ uint4  g_ap[MT * 8 * 32];
__device__ uint2  g_w1p[8 * 32 * 32];
__device__ float g_asrc[NN * 4];
__device__ float g_adst[NN * 4];
__device__ float g_asrc2[NN * 2];
__device__ float g_adst2[NN * 2];
__device__ int   g_cnt[NN];                 // zero at load; re-zeroed by agg2 tail
__device__ int   g_off[NN + 1];
__device__ int   g_cur[NN];
__device__ int   g_csr[ET];
__device__ float g_sums[GG * 32];
__device__ float g_gcnt[GG];
__device__ int   g_done;                    // agg2 completion counter

__device__ __forceinline__ float lrelu(float v) { return v > 0.f ? v : 0.2f * v; }
__device__ __forceinline__ float warp_sum(float v) {
#pragma unroll
    for (int o = 16; o > 0; o >>= 1) v += __shfl_xor_sync(FULL, v, o);
    return v;
}
__device__ __forceinline__ unsigned int packh2(float a, float b) {
    half2 h = __floats2half2_rn(a, b);
    return *(unsigned int*)&h;
}
__device__ __forceinline__ void mma16816(float& c0, float& c1, float& c2, float& c3,
                                         unsigned int a0, unsigned int a1,
                                         unsigned int a2, unsigned int a3,
                                         unsigned int b0, unsigned int b1) {
    asm volatile(
        "mma.sync.aligned.m16n8k16.row.col.f32.f16.f16.f32 "
        "{%0,%1,%2,%3}, {%4,%5,%6,%7}, {%8,%9}, {%0,%1,%2,%3};"
        : "+f"(c0), "+f"(c1), "+f"(c2), "+f"(c3)
        : "r"(a0), "r"(a1), "r"(a2), "r"(a3), "r"(b0), "r"(b1));
}

#define SPLAT2(out, f) asm("mov.b64 %0, {%1, %1};" : "=l"(out) : "r"(__float_as_uint(f)))
#define FMA2(acc, a, b) asm("fma.rn.f32x2 %0, %1, %2, %0;" : "+l"(acc) : "l"(a), "l"(b))
#define UNPACK2(lo, hi, in) asm("mov.b64 {%0, %1}, %2;" : "=r"(lo), "=r"(hi) : "l"(in))

// ---------------- prep: pack A frags, pack B frags, degree count ----------
__global__ void k_prep(const float* __restrict__ x, const float* __restrict__ W1,
                       const int* __restrict__ dst, int* __restrict__ cnt) {
    int b = blockIdx.x, t = threadIdx.x;
    if (b < APACK_BLOCKS) {
        int gid = b * 256 + t;
        int lane = gid & 31;
        int ks = (gid >> 5) & 7;
        int mt = gid >> 8;
        int gr = lane >> 2, ct = lane & 3;
        int r0 = mt * 16 + gr;
        const float2* x2 = (const float2*)x;
        float2 p00 = x2[r0 * 64 + ks * 8 + ct];
        float2 p01 = x2[r0 * 64 + ks * 8 + ct + 4];
        float2 p10 = x2[(r0 + 8) * 64 + ks * 8 + ct];
        float2 p11 = x2[(r0 + 8) * 64 + ks * 8 + ct + 4];
        uint4 frag;
        frag.x = packh2(p00.x, p00.y);
        frag.y = packh2(p10.x, p10.y);
        frag.z = packh2(p01.x, p01.y);
        frag.w = packh2(p11.x, p11.y);
        g_ap[(mt * 8 + ks) * 32 + lane] = frag;
    } else if (b < APACK_BLOCKS + BPACK_BLOCKS) {
        int gid = (b - APACK_BLOCKS) * 256 + t;
        int lane = gid & 31;
        int ntg = (gid >> 5) & 31;
        int ks = gid >> 10;
        int gr = lane >> 2, ct = lane & 3;
        int col = ntg * 8 + gr;
        int k0 = ks * 16 + 2 * ct;
        uint2 frag;
        frag.x = packh2(W1[k0 * 256 + col],       W1[(k0 + 1) * 256 + col]);
        frag.y = packh2(W1[(k0 + 8) * 256 + col], W1[(k0 + 9) * 256 + col]);
        g_w1p[(ks * 32 + ntg) * 32 + lane] = frag;
    } else {
        int gid = (b - APACK_BLOCKS - BPACK_BLOCKS) * 256 + t;
        if (gid < EE / 4) {
            int4 d4 = ((const int4*)dst)[gid];
            atomicAdd(&cnt[d4.x], 1);
            atomicAdd(&cnt[d4.y], 1);
            atomicAdd(&cnt[d4.z], 1);
            atomicAdd(&cnt[d4.w], 1);
        }
    }
}

// ---------------- scan (+1 self-loop; zero pooling buffers) ----------------
__global__ void k_scan(const int* __restrict__ cnt, int* __restrict__ off,
                       int* __restrict__ cur, float* __restrict__ sums,
                       float* __restrict__ gcnt) {
    __shared__ int ssum[1024];
    const int CH = 20;
    int t = threadIdx.x;
    sums[t] = 0.f; sums[t + 1024] = 0.f;
    if (t < GG) gcnt[t] = 0.f;
    int base = t * CH;
    int local[CH];
    int s = 0;
#pragma unroll
    for (int j = 0; j < CH; j++) {
        int v = (base + j < NN) ? (cnt[base + j] + 1) : 0;
        local[j] = s;
        s += v;
    }
    ssum[t] = s;
    __syncthreads();
    for (int o = 1; o < 1024; o <<= 1) {
        int v = (t >= o) ? ssum[t - o] : 0;
        __syncthreads();
        ssum[t] += v;
        __syncthreads();
    }
    int pre = ssum[t] - s;
#pragma unroll
    for (int j = 0; j < CH; j++) {
        if (base + j < NN) { off[base + j] = pre + local[j]; cur[base + j] = pre + local[j]; }
    }
    if (t == 1023) off[NN] = ssum[1023];
}

// ---------------- fused: tensor-core GEMM1 + att1  |  CSR build ------------
__global__ void __launch_bounds__(256) k_mma_build(
        const float* __restrict__ as1, const float* __restrict__ ad1,
        __half* __restrict__ h, float* __restrict__ asrc, float* __restrict__ adst,
        const int* __restrict__ src, const int* __restrict__ dst,
        int* __restrict__ cur, int* __restrict__ csr) {
    if (blockIdx.x >= MMA_BLOCKS) {
        // CSR fill branch
        int t = (blockIdx.x - MMA_BLOCKS) * 256 + threadIdx.x;
        if (t < EE / 4) {
            int4 s4 = ((const int4*)src)[t];
            int4 d4 = ((const int4*)dst)[t];
            csr[atomicAdd(&cur[d4.x], 1)] = s4.x;
            csr[atomicAdd(&cur[d4.y], 1)] = s4.y;
            csr[atomicAdd(&cur[d4.z], 1)] = s4.z;
            csr[atomicAdd(&cur[d4.w], 1)] = s4.w;
        } else {
            int n = t - EE / 4;
            if (n < NN) csr[atomicAdd(&cur[n], 1)] = n;
        }
        return;
    }

    int gw = blockIdx.x * 8 + (threadIdx.x >> 5);
    int lane = threadIdx.x & 31;
    int mt = gw >> 2;
    int w = gw & 3;
    if (mt >= MT) return;
    int gr = lane >> 2, ct = lane & 3;
    int row0 = mt * 16;

    uint4 a[8];
#pragma unroll
    for (int ks = 0; ks < 8; ks++) a[ks] = g_ap[(mt * 8 + ks) * 32 + lane];

    float sr = 0.f, sr8 = 0.f, dr = 0.f, dr8 = 0.f;
    half2* h2out = (half2*)h;

#pragma unroll
    for (int nt = 0; nt < 8; nt++) {
        int ntg = w * 8 + nt;
        float c0 = 0.f, c1 = 0.f, c2 = 0.f, c3 = 0.f;
#pragma unroll
        for (int ks = 0; ks < 8; ks++) {
            uint2 bfr = g_w1p[(ks * 32 + ntg) * 32 + lane];
            mma16816(c0, c1, c2, c3, a[ks].x, a[ks].y, a[ks].z, a[ks].w,
                     bfr.x, bfr.y);
        }
        h2out[(row0 + gr) * 128 + w * 32 + nt * 4 + ct]     = __floats2half2_rn(c0, c1);
        h2out[(row0 + gr + 8) * 128 + w * 32 + nt * 4 + ct] = __floats2half2_rn(c2, c3);
        float2 av = ((const float2*)as1)[w * 32 + nt * 4 + ct];
        float2 dv = ((const float2*)ad1)[w * 32 + nt * 4 + ct];
        sr  += c0 * av.x + c1 * av.y;
        sr8 += c2 * av.x + c3 * av.y;
        dr  += c0 * dv.x + c1 * dv.y;
        dr8 += c2 * dv.x + c3 * dv.y;
    }
    sr  += __shfl_xor_sync(FULL, sr, 1);  sr  += __shfl_xor_sync(FULL, sr, 2);
    sr8 += __shfl_xor_sync(FULL, sr8, 1); sr8 += __shfl_xor_sync(FULL, sr8, 2);
    dr  += __shfl_xor_sync(FULL, dr, 1);  dr  += __shfl_xor_sync(FULL, dr, 2);
    dr8 += __shfl_xor_sync(FULL, dr8, 1); dr8 += __shfl_xor_sync(FULL, dr8, 2);
    if (ct == 0) {
        asrc[(row0 + gr) * 4 + w] = sr;
        asrc[(row0 + gr + 8) * 4 + w] = sr8;
        adst[(row0 + gr) * 4 + w] = dr;
        adst[(row0 + gr + 8) * 4 + w] = dr8;
    }
}

// ---------------- layer 1 aggregation (fp16 gather) -> x1 fp16 -------------
__global__ void k_agg1(const int* __restrict__ off, const int* __restrict__ csr,
                       const __half* __restrict__ hfeat, const float* __restrict__ asrc,
                       const float* __restrict__ adst, const float* __restrict__ bias,
                       __half* __restrict__ x1out) {
    __shared__ int    sm_s[8][32];
    __shared__ float4 sm_w[8][32];
    int wid = threadIdx.x >> 5;
    int lane = threadIdx.x & 31;
    int d = blockIdx.x * 8 + wid;
    if (d >= NN) return;
    int b0 = off[d], b1 = off[d + 1];

    float4 adv = ((const float4*)adst)[d];
    int hh = lane >> 3;

    float s0 = 0.f, s1 = 0.f, s2 = 0.f, s3 = 0.f;
    float acc[8];
#pragma unroll
    for (int j = 0; j < 8; j++) acc[j] = 0.f;

    const uint4* hf = (const uint4*)hfeat;
    const float4* as4 = (const float4*)asrc;
    const float* wp = (const float*)&sm_w[wid][0];

    for (int base = b0; base < b1; base += 32) {
        int k = base + lane;
        float4 w = make_float4(0.f, 0.f, 0.f, 0.f);
        int sidx = 0;
        if (k < b1) {
            sidx = csr[k];
            float4 a = as4[sidx];
            w.x = __expf(lrelu(a.x + adv.x));
            w.y = __expf(lrelu(a.y + adv.y));
            w.z = __expf(lrelu(a.z + adv.z));
            w.w = __expf(lrelu(a.w + adv.w));
            s0 += w.x; s1 += w.y; s2 += w.z; s3 += w.w;
        }
        sm_s[wid][lane] = sidx;
        sm_w[wid][lane] = w;
        __syncwarp();
        int cnt = min(32, b1 - base);
        for (int e = 0; e < cnt; e++) {
            int ss = sm_s[wid][e];
            float we = wp[e * 4 + hh];
            uint4 v = hf[ss * 32 + lane];
            float2 p;
            p = __half22float2(*(half2*)&v.x); acc[0] = fmaf(we, p.x, acc[0]); acc[1] = fmaf(we, p.y, acc[1]);
            p = __half22float2(*(half2*)&v.y); acc[2] = fmaf(we, p.x, acc[2]); acc[3] = fmaf(we, p.y, acc[3]);
            p = __half22float2(*(half2*)&v.z); acc[4] = fmaf(we, p.x, acc[4]); acc[5] = fmaf(we, p.y, acc[5]);
            p = __half22float2(*(half2*)&v.w); acc[6] = fmaf(we, p.x, acc[6]); acc[7] = fmaf(we, p.y, acc[7]);
        }
        __syncwarp();
    }

    s0 = warp_sum(s0); s1 = warp_sum(s1); s2 = warp_sum(s2); s3 = warp_sum(s3);
    float iH = (hh == 0) ? 1.f / (s0 + 1e-16f)
             : (hh == 1) ? 1.f / (s1 + 1e-16f)
             : (hh == 2) ? 1.f / (s2 + 1e-16f)
             :             1.f / (s3 + 1e-16f);
#pragma unroll
    for (int j = 0; j < 8; j++) acc[j] *= iH;

#pragma unroll
    for (int j = 0; j < 8; j++) {
        acc[j] += __shfl_xor_sync(FULL, acc[j], 8);
        acc[j] += __shfl_xor_sync(FULL, acc[j], 16);
    }
    if (lane < 8) {
        float4 bb0 = ((const float4*)bias)[lane * 2];
        float4 bb1 = ((const float4*)bias)[lane * 2 + 1];
        uint4 pk;
        pk.x = packh2(fmaxf(acc[0] * 0.25f + bb0.x, 0.f), fmaxf(acc[1] * 0.25f + bb0.y, 0.f));
        pk.y = packh2(fmaxf(acc[2] * 0.25f + bb0.z, 0.f), fmaxf(acc[3] * 0.25f + bb0.w, 0.f));
        pk.z = packh2(fmaxf(acc[4] * 0.25f + bb1.x, 0.f), fmaxf(acc[5] * 0.25f + bb1.y, 0.f));
        pk.w = packh2(fmaxf(acc[6] * 0.25f + bb1.z, 0.f), fmaxf(acc[7] * 0.25f + bb1.w, 0.f));
        ((uint4*)x1out)[d * 8 + lane] = pk;
    }
}

// ---------------- GEMM2: 128 nodes/block, 4-node W amortization ------------
__global__ void __launch_bounds__(256) k_gemm2(
        const __half* __restrict__ x1, const float* __restrict__ W2,
        const float* __restrict__ as2, const float* __restrict__ ad2,
        __half* __restrict__ h2out, float* __restrict__ asrc2,
        float* __restrict__ adst2) {
    __shared__ float  smW[64 * 64];
    __shared__ __half smX[128 * 68];
    int t = threadIdx.x;
    int n0 = blockIdx.x * 128;

#pragma unroll
    for (int i = 0; i < 4; i++)
        ((float4*)smW)[t + 256 * i] = ((const float4*)W2)[t + 256 * i];
    {
        int row = t >> 1, part = t & 1;
        int n = n0 + row;
        const uint4* gsrc = (const uint4*)x1 + (long long)n * 8 + part * 4;
        uint2* drow = (uint2*)(smX + row * 68 + part * 32);
#pragma unroll
        for (int i = 0; i < 4; i++) {
            uint4 v = (n < NN) ? gsrc[i] : make_uint4(0, 0, 0, 0);
            drow[2 * i]     = make_uint2(v.x, v.y);
            drow[2 * i + 1] = make_uint2(v.z, v.w);
        }
    }
    __syncthreads();

    int grp = t >> 3;
    int cg  = t & 7;
    int nl0 = grp * 4;

    unsigned long long acc[4][4];
#pragma unroll
    for (int r = 0; r < 4; r++)
#pragma unroll
        for (int j = 0; j < 4; j++) acc[r][j] = 0ull;

    const ulonglong2* Wr = (const ulonglong2*)smW;
#pragma unroll 4
    for (int k = 0; k < 64; k++) {
        ulonglong2 w0 = Wr[k * 16 + cg * 2];
        ulonglong2 w1 = Wr[k * 16 + cg * 2 + 1];
#pragma unroll
        for (int r = 0; r < 4; r++) {
            float xv = __half2float(smX[(nl0 + r) * 68 + k]);
            unsigned long long xs; SPLAT2(xs, xv);
            FMA2(acc[r][0], xs, w0.x); FMA2(acc[r][1], xs, w0.y);
            FMA2(acc[r][2], xs, w1.x); FMA2(acc[r][3], xs, w1.y);
        }
    }

    int hd = cg >> 2;
    const float4* a4 = (const float4*)(as2 + hd * 32 + (cg & 3) * 8);
    const float4* d4v = (const float4*)(ad2 + hd * 32 + (cg & 3) * 8);
    float4 aa0 = a4[0], aa1 = a4[1];
    float4 dd0 = d4v[0], dd1 = d4v[1];

#pragma unroll
    for (int r = 0; r < 4; r++) {
        int d = n0 + nl0 + r;
        float c[8];
        unsigned int lo, hi;
        UNPACK2(lo, hi, acc[r][0]); c[0] = __uint_as_float(lo); c[1] = __uint_as_float(hi);
        UNPACK2(lo, hi, acc[r][1]); c[2] = __uint_as_float(lo); c[3] = __uint_as_float(hi);
        UNPACK2(lo, hi, acc[r][2]); c[4] = __uint_as_float(lo); c[5] = __uint_as_float(hi);
        UNPACK2(lo, hi, acc[r][3]); c[6] = __uint_as_float(lo); c[7] = __uint_as_float(hi);
        float ps = c[0]*aa0.x + c[1]*aa0.y + c[2]*aa0.z + c[3]*aa0.w
                 + c[4]*aa1.x + c[5]*aa1.y + c[6]*aa1.z + c[7]*aa1.w;
        float pd = c[0]*dd0.x + c[1]*dd0.y + c[2]*dd0.z + c[3]*dd0.w
                 + c[4]*dd1.x + c[5]*dd1.y + c[6]*dd1.z + c[7]*dd1.w;
        ps += __shfl_xor_sync(FULL, ps, 1);
        ps += __shfl_xor_sync(FULL, ps, 2);
        pd += __shfl_xor_sync(FULL, pd, 1);
        pd += __shfl_xor_sync(FULL, pd, 2);
        if (d < NN) {
            uint4 pk;
            pk.x = packh2(c[0], c[1]);
            pk.y = packh2(c[2], c[3]);
            pk.z = packh2(c[4], c[5]);
            pk.w = packh2(c[6], c[7]);
            ((uint4*)h2out)[d * 8 + cg] = pk;
            if ((cg & 3) == 0) {
                asrc2[d * 2 + hd] = ps;
                adst2[d * 2 + hd] = pd;
            }
        }
    }
}

// ---------------- layer 2 aggregation + pool + fused heads (last block) ----
__global__ void k_agg2(const int* __restrict__ off, const int* __restrict__ csr,
                       const __half* __restrict__ hfeat, const float* __restrict__ asrc,
                       const float* __restrict__ adst, const float* __restrict__ bias,
                       const int* __restrict__ batch, float* __restrict__ sums,
                       float* __restrict__ gcnt,
                       const float* __restrict__ cW1, const float* __restrict__ cb1,
                       const float* __restrict__ cW2, const float* __restrict__ cb2,
                       const float* __restrict__ hW1, const float* __restrict__ hb1,
                       const float* __restrict__ hW2, const float* __restrict__ hb2,
                       float* __restrict__ out, int* __restrict__ cntz,
                       int* __restrict__ done) {
    __shared__ int    sm_s[8][32];
    __shared__ float2 sm_w[8][32];
    __shared__ int sm_last;
    int wid = threadIdx.x >> 5;
    int lane = threadIdx.x & 31;
    int d = blockIdx.x * 8 + wid;

    if (d < NN) {
        int b0 = off[d], b1 = off[d + 1];
        float2 adv = ((const float2*)adst)[d];
        int hh = lane >> 4;
        float s0 = 0.f, s1 = 0.f;
        float2 acc = make_float2(0.f, 0.f);
        const half2* hf = (const half2*)hfeat;
        const float2* as2p = (const float2*)asrc;
        const float* wp = (const float*)&sm_w[wid][0];

        for (int base = b0; base < b1; base += 32) {
            int k = base + lane;
            float2 w = make_float2(0.f, 0.f);
            int sidx = 0;
            if (k < b1) {
                sidx = csr[k];
                float2 a = as2p[sidx];
                w.x = __expf(lrelu(a.x + adv.x));
                w.y = __expf(lrelu(a.y + adv.y));
                s0 += w.x; s1 += w.y;
            }
            sm_s[wid][lane] = sidx;
            sm_w[wid][lane] = w;
            __syncwarp();
            int cnt = min(32, b1 - base);
            for (int e = 0; e < cnt; e++) {
                int ss = sm_s[wid][e];
                float we = wp[e * 2 + hh];
                float2 v = __half22float2(hf[ss * 32 + lane]);
                acc.x = fmaf(we, v.x, acc.x);
                acc.y = fmaf(we, v.y, acc.y);
            }
            __syncwarp();
        }

        s0 = warp_sum(s0); s1 = warp_sum(s1);
        float iH = hh ? 1.f / (s1 + 1e-16f) : 1.f / (s0 + 1e-16f);
        acc.x *= iH;
        acc.y *= iH;
        acc.x += __shfl_xor_sync(FULL, acc.x, 16);
        acc.y += __shfl_xor_sync(FULL, acc.y, 16);
        if (lane < 16) {
            const float2 b = ((const float2*)bias)[lane];
            float ox = fmaxf(acc.x * 0.5f + b.x, 0.f);
            float oy = fmaxf(acc.y * 0.5f + b.y, 0.f);
            int g = batch[d];
            atomicAdd(&sums[g * 32 + 2 * lane], ox);
            atomicAdd(&sums[g * 32 + 2 * lane + 1], oy);
            if (lane == 0) atomicAdd(&gcnt[g], 1.f);
        }
    }

    // ---- last-block-done: fused heads ----
    __threadfence();
    __syncthreads();
    if (threadIdx.x == 0)
        sm_last = (atomicAdd(done, 1) == gridDim.x - 1) ? 1 : 0;
    __syncthreads();
    if (!sm_last) return;

    int t = threadIdx.x;
    // re-zero degree counters + done flag for next graph replay
    int4 z = make_int4(0, 0, 0, 0);
    for (int i = t; i < NN / 4; i += 256) ((int4*)cntz)[i] = z;
    if (t == 0) *done = 0;

    if (t < GG) {
        int g = t;
        float emb[32];
        float c_ = __ldcg(&gcnt[g]);
        c_ = (c_ > 1.f) ? c_ : 1.f;
        for (int c = 0; c < 32; c++) emb[c] = __ldcg(&sums[g * 32 + c]) / c_;
        float oh = hb2[0], oc = cb2[0];
        for (int j = 0; j < 16; j++) {
            float sh = hb1[j], sc = cb1[j];
            for (int c = 0; c < 32; c++) {
                sh = fmaf(emb[c], hW1[c * 16 + j], sh);
                sc = fmaf(emb[c], cW1[c * 16 + j], sc);
            }
            sh = fmaxf(sh, 0.f);
            sc = fmaxf(sc, 0.f);
            oh = fmaf(sh, hW2[j], oh);
            oc = fmaf(sc, cW2[j], oc);
        }
        out[g]      = 1.f / (1.f + __expf(-oh));
        out[GG + g] = 1.f / (1.f + __expf(-oc));
    }
}

// ---------------- host ----------------
static inline int cdiv(long long a, int b) { return (int)((a + b - 1) / b); }

extern "C" void kernel_launch(void* const* d_in, const int* in_sizes, int n_in,
                              void* d_out, int out_size) {
    const float* x     = (const float*)d_in[0];
    const int*   ei    = (const int*)  d_in[1];
    const int*   batch = (const int*)  d_in[2];
    const float* W1  = (const float*)d_in[3];
    const float* as1 = (const float*)d_in[4];
    const float* ad1 = (const float*)d_in[5];
    const float* b1  = (const float*)d_in[6];
    const float* W2  = (const float*)d_in[7];
    const float* as2 = (const float*)d_in[8];
    const float* ad2 = (const float*)d_in[9];
    const float* b2  = (const float*)d_in[10];
    const float* cW1 = (const float*)d_in[11];
    const float* cb1 = (const float*)d_in[12];
    const float* cW2 = (const float*)d_in[13];
    const float* cb2 = (const float*)d_in[14];
    const float* hW1 = (const float*)d_in[15];
    const float* hb1 = (const float*)d_in[16];
    const float* hW2 = (const float*)d_in[17];
    const float* hb2 = (const float*)d_in[18];

    const int* src = ei;
    const int* dst = ei + EE;

    __half *p_h, *p_x1, *p_h2;
    float *p_asrc, *p_adst, *p_asrc2, *p_adst2, *p_sums, *p_gcnt;
    int *p_cnt, *p_off, *p_cur, *p_csr, *p_done;
    cudaGetSymbolAddress((void**)&p_h, g_h);
    cudaGetSymbolAddress((void**)&p_x1, g_x1);
    cudaGetSymbolAddress((void**)&p_h2, g_h2);
    cudaGetSymbolAddress((void**)&p_asrc, g_asrc);
    cudaGetSymbolAddress((void**)&p_adst, g_adst);
    cudaGetSymbolAddress((void**)&p_asrc2, g_asrc2);
    cudaGetSymbolAddress((void**)&p_adst2, g_adst2);
    cudaGetSymbolAddress((void**)&p_cnt, g_cnt);
    cudaGetSymbolAddress((void**)&p_off, g_off);
    cudaGetSymbolAddress((void**)&p_cur, g_cur);
    cudaGetSymbolAddress((void**)&p_csr, g_csr);
    cudaGetSymbolAddress((void**)&p_sums, g_sums);
    cudaGetSymbolAddress((void**)&p_gcnt, g_gcnt);
    cudaGetSymbolAddress((void**)&p_done, g_done);

    const int T = 256;

    // g_cnt zero at entry (load-time zero / re-zeroed by agg2 tail)
    k_prep<<<APACK_BLOCKS + BPACK_BLOCKS + COUNT_BLOCKS, T>>>(x, W1, dst, p_cnt);
    k_scan<<<1, 1024>>>(p_cnt, p_off, p_cur, p_sums, p_gcnt);
    // GEMM1(+att1) and CSR build in one launch (independent block ranges)
    k_mma_build<<<MMA_BLOCKS + BUILD_BLOCKS, T>>>(as1, ad1, p_h, p_asrc, p_adst,
                                                  src, dst, p_cur, p_csr);
    k_agg1<<<cdiv(NN, 8), T>>>(p_off, p_csr, p_h, p_asrc, p_adst, b1, p_x1);
    k_gemm2<<<cdiv(NN, 128), T>>>(p_x1, W2, as2, ad2, p_h2, p_asrc2, p_adst2);
    k_agg2<<<AGG2_BLOCKS, T>>>(p_off, p_csr, p_h2, p_asrc2, p_adst2, b2,
                               batch, p_sums, p_gcnt,
                               cW1, cb1, cW2, cb2, hW1, hb1, hW2, hb2,
                               (float*)d_out, p_cnt, p_done);
}